// round 4
// baseline (speedup 1.0000x reference)
#include <cuda_runtime.h>
#include <cstdint>

#define B_TOT 16384
#define F 39
#define E 16
#define D 16
#define NT 128
#define PS 20   // padded row stride (floats), 16B-aligned rows

// transposed-weight offsets in sWT (stride PS, [j][i] layout, 16 rows each = 320 floats)
#define WT_Q 0
#define WT_K 320
#define WT_V 656
#define WT_R 976
#define WT_SZ 1296

// projection offsets in sproj (stride PS, 39 rows each = 780 floats)
#define OFF_Q 0
#define OFF_K 784
#define OFF_V 1584
#define OFF_R 2368
#define SPROJ_SZ 3148

__device__ __forceinline__ void fma2(uint64_t& d, uint64_t a, uint64_t b) {
    asm("fma.rn.f32x2 %0, %1, %2, %0;" : "+l"(d) : "l"(a), "l"(b));
}
__device__ __forceinline__ uint64_t add2(uint64_t a, uint64_t b) {
    uint64_t r; asm("add.rn.f32x2 %0, %1, %2;" : "=l"(r) : "l"(a), "l"(b)); return r;
}
__device__ __forceinline__ uint64_t pk2(float lo, float hi) {
    uint64_t r; asm("mov.b64 %0, {%1, %2};" : "=l"(r) : "f"(lo), "f"(hi)); return r;
}
__device__ __forceinline__ float hadd2(uint64_t p) {
    float lo, hi; asm("mov.b64 {%0, %1}, %2;" : "=f"(lo), "=f"(hi) : "l"(p)); return lo + hi;
}
__device__ __forceinline__ void unpk2(uint64_t p, float& lo, float& hi) {
    asm("mov.b64 {%0, %1}, %2;" : "=f"(lo), "=f"(hi) : "l"(p));
}

__global__ __launch_bounds__(NT)
void self_attn_interaction_kernel(
    const float* __restrict__ x,
    const float* __restrict__ Wq,
    const float* __restrict__ Wk,
    const float* __restrict__ Wv,
    const float* __restrict__ Wr,
    float* __restrict__ out)
{
    __shared__ __align__(16) float sWT[WT_SZ];
    __shared__ __align__(16) float sx[F * E];
    __shared__ __align__(16) float sproj[SPROJ_SZ];

    const int t = threadIdx.x;
    const int b = blockIdx.x;
    const float* xb = x + (size_t)b * (F * E);

    // ---- stage: weights (transposed into [j][i]) + x ----
    for (int e = t; e < E * D; e += NT) {
        const int i = e >> 4, j = e & 15;
        const int o = j * PS + i;
        sWT[WT_Q + o] = Wq[e];
        sWT[WT_K + o] = Wk[e];
        sWT[WT_V + o] = Wv[e];
        sWT[WT_R + o] = Wr[e];
    }
    {
        const float4* x4 = (const float4*)xb;
        float4* sx4 = (float4*)sx;
        for (int i = t; i < (F * E) / 4; i += NT) sx4[i] = x4[i];
    }
    __syncthreads();

    // ---- phase 1: projections (packed f32x2, weights register-resident) ----
    {
        const int j  = t & 15;
        const int s  = t >> 4;
        const int p  = s & 1;          // 0 -> {Q,K}, 1 -> {V,Res}
        const int f0 = s >> 1;         // 0..3
        const ulonglong2* wta = (const ulonglong2*)(sWT + (p ? WT_V : WT_Q) + j * PS);
        const ulonglong2* wtb = (const ulonglong2*)(sWT + (p ? WT_R : WT_K) + j * PS);
        float* outA = sproj + (p ? OFF_V : OFF_Q);
        float* outB = sproj + (p ? OFF_R : OFF_K);

        uint64_t wa[8], wb[8];
        #pragma unroll
        for (int u = 0; u < 4; u++) {
            ulonglong2 a = wta[u], c = wtb[u];
            wa[2 * u] = a.x; wa[2 * u + 1] = a.y;
            wb[2 * u] = c.x; wb[2 * u + 1] = c.y;
        }
        for (int f = f0; f < F; f += 4) {
            const ulonglong2* xr2 = (const ulonglong2*)(sx + f * 16);
            uint64_t xp[8];
            #pragma unroll
            for (int u = 0; u < 4; u++) {
                ulonglong2 v = xr2[u];
                xp[2 * u] = v.x; xp[2 * u + 1] = v.y;
            }
            uint64_t accA = 0ull, accB = 0ull;
            #pragma unroll
            for (int i = 0; i < 8; i++) {
                fma2(accA, xp[i], wa[i]);
                fma2(accB, xp[i], wb[i]);
            }
            outA[f * PS + j] = hadd2(accA);
            outB[f * PS + j] = hadd2(accB);
        }
    }
    __syncthreads();

    // ---- fused phase 2+3: warp-per-head streaming softmax-attention ----
    // warp h owns head h. lane l owns row l; lanes 0..6 also own row l+32.
    // K/V loads inside the g-loop are single-address broadcasts (1 wf each).
    const int w = t >> 5;
    if (w < 2) {
        const int h = w;
        const int l = t & 31;
        const int f0 = l;
        const int f1 = l + 32;
        const bool two = (f1 < F);

        const ulonglong2* q2a = (const ulonglong2*)(sproj + OFF_Q + f0 * PS + h * 8);
        ulonglong2 qa = q2a[0], qb = q2a[1];
        uint64_t q00 = qa.x, q01 = qa.y, q02 = qb.x, q03 = qb.y;

        uint64_t q10 = 0, q11 = 0, q12 = 0, q13 = 0;
        if (two) {
            const ulonglong2* q2b = (const ulonglong2*)(sproj + OFF_Q + f1 * PS + h * 8);
            ulonglong2 qc = q2b[0], qd = q2b[1];
            q10 = qc.x; q11 = qc.y; q12 = qd.x; q13 = qd.y;
        }

        uint64_t a00 = 0, a01 = 0, a02 = 0, a03 = 0;
        uint64_t a10 = 0, a11 = 0, a12 = 0, a13 = 0;
        float sum0 = 0.f, sum1 = 0.f;

        const float* kbase = sproj + OFF_K + h * 8;
        const float* vbase = sproj + OFF_V + h * 8;

        #pragma unroll 3
        for (int g = 0; g < F; g++) {
            const ulonglong2* k2 = (const ulonglong2*)(kbase + g * PS);
            const ulonglong2* v2 = (const ulonglong2*)(vbase + g * PS);
            ulonglong2 ku = k2[0], kv = k2[1];
            ulonglong2 vu = v2[0], vv = v2[1];

            // row 0
            {
                uint64_t sp0 = 0ull, sp1 = 0ull;
                fma2(sp0, q00, ku.x); fma2(sp1, q01, ku.y);
                fma2(sp0, q02, kv.x); fma2(sp1, q03, kv.y);
                float e = __expf(hadd2(add2(sp0, sp1)));
                sum0 += e;
                uint64_t ee = pk2(e, e);
                fma2(a00, ee, vu.x); fma2(a01, ee, vu.y);
                fma2(a02, ee, vv.x); fma2(a03, ee, vv.y);
            }
            // row 1 (predicated)
            if (two) {
                uint64_t sp0 = 0ull, sp1 = 0ull;
                fma2(sp0, q10, ku.x); fma2(sp1, q11, ku.y);
                fma2(sp0, q12, kv.x); fma2(sp1, q13, kv.y);
                float e = __expf(hadd2(add2(sp0, sp1)));
                sum1 += e;
                uint64_t ee = pk2(e, e);
                fma2(a10, ee, vu.x); fma2(a11, ee, vu.y);
                fma2(a12, ee, vv.x); fma2(a13, ee, vv.y);
            }
        }

        float* obase = out + (size_t)b * (F * E);

        // epilogue row 0
        {
            const float rinv = __fdividef(1.f, sum0);
            const uint64_t rp = pk2(rinv, rinv);
            const ulonglong2* r2 = (const ulonglong2*)(sproj + OFF_R + f0 * PS + h * 8);
            ulonglong2 ru = r2[0], rv = r2[1];
            uint64_t o0 = ru.x, o1 = ru.y, o2 = rv.x, o3 = rv.y;
            fma2(o0, a00, rp); fma2(o1, a01, rp);
            fma2(o2, a02, rp); fma2(o3, a03, rp);
            float4 w0, w1;
            unpk2(o0, w0.x, w0.y); unpk2(o1, w0.z, w0.w);
            unpk2(o2, w1.x, w1.y); unpk2(o3, w1.z, w1.w);
            w0.x = fmaxf(w0.x, 0.f); w0.y = fmaxf(w0.y, 0.f);
            w0.z = fmaxf(w0.z, 0.f); w0.w = fmaxf(w0.w, 0.f);
            w1.x = fmaxf(w1.x, 0.f); w1.y = fmaxf(w1.y, 0.f);
            w1.z = fmaxf(w1.z, 0.f); w1.w = fmaxf(w1.w, 0.f);
            float* ob = obase + f0 * 16 + h * 8;
            ((float4*)ob)[0] = w0;
            ((float4*)ob)[1] = w1;
        }
        // epilogue row 1 (predicated)
        if (two) {
            const float rinv = __fdividef(1.f, sum1);
            const uint64_t rp = pk2(rinv, rinv);
            const ulonglong2* r2 = (const ulonglong2*)(sproj + OFF_R + f1 * PS + h * 8);
            ulonglong2 ru = r2[0], rv = r2[1];
            uint64_t o0 = ru.x, o1 = ru.y, o2 = rv.x, o3 = rv.y;
            fma2(o0, a10, rp); fma2(o1, a11, rp);
            fma2(o2, a12, rp); fma2(o3, a13, rp);
            float4 w0, w1;
            unpk2(o0, w0.x, w0.y); unpk2(o1, w0.z, w0.w);
            unpk2(o2, w1.x, w1.y); unpk2(o3, w1.z, w1.w);
            w0.x = fmaxf(w0.x, 0.f); w0.y = fmaxf(w0.y, 0.f);
            w0.z = fmaxf(w0.z, 0.f); w0.w = fmaxf(w0.w, 0.f);
            w1.x = fmaxf(w1.x, 0.f); w1.y = fmaxf(w1.y, 0.f);
            w1.z = fmaxf(w1.z, 0.f); w1.w = fmaxf(w1.w, 0.f);
            float* ob = obase + f1 * 16 + h * 8;
            ((float4*)ob)[0] = w0;
            ((float4*)ob)[1] = w1;
        }
    }
}

extern "C" void kernel_launch(void* const* d_in, const int* in_sizes, int n_in,
                              void* d_out, int out_size)
{
    const float* x  = (const float*)d_in[0];
    const float* Wq = (const float*)d_in[1];
    const float* Wk = (const float*)d_in[2];
    const float* Wv = (const float*)d_in[3];
    const float* Wr = (const float*)d_in[4];
    float* out = (float*)d_out;
    self_attn_interaction_kernel<<<B_TOT, NT>>>(x, Wq, Wk, Wv, Wr, out);
}

// round 6
// speedup vs baseline: 1.2205x; 1.2205x over previous
#include <cuda_runtime.h>
#include <cstdint>

// R5 retry: identical design to the R5 submission; previous run died to a
// container-infra failure before executing.

#define B_TOT 16384
#define F 39
#define E 16
#define D 16
#define NT 128
#define PS 20   // padded row stride (floats), 16B-aligned rows

// transposed-weight offsets in sWT (stride PS, [j][i] layout, 16 rows each = 320 floats)
#define WT_Q 0
#define WT_K 320
#define WT_V 656
#define WT_R 976
#define WT_SZ 1296

// per-batch projection offsets in sproj (stride PS, 39 rows each = 780 floats)
#define OFF_Q 0
#define OFF_K 784
#define OFF_V 1584
#define OFF_R 2368
#define SPROJ_SZ 3148   // *4 bytes = 12592, 16B-aligned -> batch 1 slab stays aligned

__device__ __forceinline__ void fma2(uint64_t& d, uint64_t a, uint64_t b) {
    asm("fma.rn.f32x2 %0, %1, %2, %0;" : "+l"(d) : "l"(a), "l"(b));
}
__device__ __forceinline__ uint64_t add2(uint64_t a, uint64_t b) {
    uint64_t r; asm("add.rn.f32x2 %0, %1, %2;" : "=l"(r) : "l"(a), "l"(b)); return r;
}
__device__ __forceinline__ uint64_t pk2(float lo, float hi) {
    uint64_t r; asm("mov.b64 %0, {%1, %2};" : "=l"(r) : "f"(lo), "f"(hi)); return r;
}
__device__ __forceinline__ float hadd2(uint64_t p) {
    float lo, hi; asm("mov.b64 {%0, %1}, %2;" : "=f"(lo), "=f"(hi) : "l"(p)); return lo + hi;
}
__device__ __forceinline__ void unpk2(uint64_t p, float& lo, float& hi) {
    asm("mov.b64 {%0, %1}, %2;" : "=f"(lo), "=f"(hi) : "l"(p));
}

__global__ __launch_bounds__(NT)
void self_attn_interaction_kernel(
    const float* __restrict__ x,
    const float* __restrict__ Wq,
    const float* __restrict__ Wk,
    const float* __restrict__ Wv,
    const float* __restrict__ Wr,
    float* __restrict__ out)
{
    __shared__ __align__(16) float sWT[WT_SZ];
    __shared__ __align__(16) float sx[2 * F * E];        // 2 batches
    __shared__ __align__(16) float sproj[2 * SPROJ_SZ]; // 2 batches

    const int t = threadIdx.x;
    const int b0 = blockIdx.x * 2;
    const float* xb = x + (size_t)b0 * (F * E);

    // ---- stage: weights (transposed into [j][i]) + x for both batches ----
    for (int e = t; e < E * D; e += NT) {
        const int i = e >> 4, j = e & 15;
        const int o = j * PS + i;
        sWT[WT_Q + o] = Wq[e];
        sWT[WT_K + o] = Wk[e];
        sWT[WT_V + o] = Wv[e];
        sWT[WT_R + o] = Wr[e];
    }
    {
        const float4* x4 = (const float4*)xb;
        float4* sx4 = (float4*)sx;
        for (int i = t; i < (2 * F * E) / 4; i += NT) sx4[i] = x4[i];
    }
    __syncthreads();

    // ---- phase 1: projections for both batches ----
    // thread = (j, s): s bit0 = matrix pair, bit1 = batch, bit2 = f-half.
    // warp covers s = {2w, 2w+1} (pair bit only differs) -> x-row loads are
    // full-warp broadcasts; pair store bases are 16 banks apart.
    {
        const int j  = t & 15;
        const int s  = t >> 4;
        const int p  = s & 1;
        const int bt = (s >> 1) & 1;
        const int f0 = s >> 2;
        const float* sxb = sx + bt * (F * E);
        float* spb = sproj + bt * SPROJ_SZ;
        const ulonglong2* wta = (const ulonglong2*)(sWT + (p ? WT_V : WT_Q) + j * PS);
        const ulonglong2* wtb = (const ulonglong2*)(sWT + (p ? WT_R : WT_K) + j * PS);
        float* outA = spb + (p ? OFF_V : OFF_Q);
        float* outB = spb + (p ? OFF_R : OFF_K);

        uint64_t wa[8], wb[8];
        #pragma unroll
        for (int u = 0; u < 4; u++) {
            ulonglong2 a = wta[u], c = wtb[u];
            wa[2 * u] = a.x; wa[2 * u + 1] = a.y;
            wb[2 * u] = c.x; wb[2 * u + 1] = c.y;
        }
        for (int f = f0; f < F; f += 2) {
            const ulonglong2* xr2 = (const ulonglong2*)(sxb + f * 16);
            uint64_t xp[8];
            #pragma unroll
            for (int u = 0; u < 4; u++) {
                ulonglong2 v = xr2[u];
                xp[2 * u] = v.x; xp[2 * u + 1] = v.y;
            }
            uint64_t accA = 0ull, accB = 0ull;
            #pragma unroll
            for (int i = 0; i < 8; i++) {
                fma2(accA, xp[i], wa[i]);
                fma2(accB, xp[i], wb[i]);
            }
            outA[f * PS + j] = hadd2(accA);
            outB[f * PS + j] = hadd2(accB);
        }
    }
    __syncthreads();

    // ---- fused phase 2+3: warp-per-(batch,head) streaming softmax-attention ----
    // warp w: batch = w>>1, head = w&1. lane l owns row l; lanes 0..6 also row l+32.
    // K/V loads inside the g-loop are single-address full-warp broadcasts.
    {
        const int w  = t >> 5;
        const int bt = w >> 1;
        const int h  = w & 1;
        const int l  = t & 31;
        const int f0 = l;
        const int f1 = l + 32;
        const bool two = (f1 < F);
        const float* spb = sproj + bt * SPROJ_SZ;

        const ulonglong2* q2a = (const ulonglong2*)(spb + OFF_Q + f0 * PS + h * 8);
        ulonglong2 qa = q2a[0], qb = q2a[1];
        uint64_t q00 = qa.x, q01 = qa.y, q02 = qb.x, q03 = qb.y;

        uint64_t q10 = 0, q11 = 0, q12 = 0, q13 = 0;
        if (two) {
            const ulonglong2* q2b = (const ulonglong2*)(spb + OFF_Q + f1 * PS + h * 8);
            ulonglong2 qc = q2b[0], qd = q2b[1];
            q10 = qc.x; q11 = qc.y; q12 = qd.x; q13 = qd.y;
        }

        uint64_t a00 = 0, a01 = 0, a02 = 0, a03 = 0;
        uint64_t a10 = 0, a11 = 0, a12 = 0, a13 = 0;
        float sum0 = 0.f, sum1 = 0.f;

        const float* kbase = spb + OFF_K + h * 8;
        const float* vbase = spb + OFF_V + h * 8;

        #pragma unroll 3
        for (int g = 0; g < F; g++) {
            const ulonglong2* k2 = (const ulonglong2*)(kbase + g * PS);
            const ulonglong2* v2 = (const ulonglong2*)(vbase + g * PS);
            ulonglong2 ku = k2[0], kv = k2[1];
            ulonglong2 vu = v2[0], vv = v2[1];

            // row 0
            {
                uint64_t sp0 = 0ull, sp1 = 0ull;
                fma2(sp0, q00, ku.x); fma2(sp1, q01, ku.y);
                fma2(sp0, q02, kv.x); fma2(sp1, q03, kv.y);
                float e = __expf(hadd2(add2(sp0, sp1)));
                sum0 += e;
                uint64_t ee = pk2(e, e);
                fma2(a00, ee, vu.x); fma2(a01, ee, vu.y);
                fma2(a02, ee, vv.x); fma2(a03, ee, vv.y);
            }
            // row 1 (predicated)
            if (two) {
                uint64_t sp0 = 0ull, sp1 = 0ull;
                fma2(sp0, q10, ku.x); fma2(sp1, q11, ku.y);
                fma2(sp0, q12, kv.x); fma2(sp1, q13, kv.y);
                float e = __expf(hadd2(add2(sp0, sp1)));
                sum1 += e;
                uint64_t ee = pk2(e, e);
                fma2(a10, ee, vu.x); fma2(a11, ee, vu.y);
                fma2(a12, ee, vv.x); fma2(a13, ee, vv.y);
            }
        }

        float* obase = out + (size_t)(b0 + bt) * (F * E);

        // epilogue row 0
        {
            const float rinv = __fdividef(1.f, sum0);
            const uint64_t rp = pk2(rinv, rinv);
            const ulonglong2* r2 = (const ulonglong2*)(spb + OFF_R + f0 * PS + h * 8);
            ulonglong2 ru = r2[0], rv = r2[1];
            uint64_t o0 = ru.x, o1 = ru.y, o2 = rv.x, o3 = rv.y;
            fma2(o0, a00, rp); fma2(o1, a01, rp);
            fma2(o2, a02, rp); fma2(o3, a03, rp);
            float4 w0, w1;
            unpk2(o0, w0.x, w0.y); unpk2(o1, w0.z, w0.w);
            unpk2(o2, w1.x, w1.y); unpk2(o3, w1.z, w1.w);
            w0.x = fmaxf(w0.x, 0.f); w0.y = fmaxf(w0.y, 0.f);
            w0.z = fmaxf(w0.z, 0.f); w0.w = fmaxf(w0.w, 0.f);
            w1.x = fmaxf(w1.x, 0.f); w1.y = fmaxf(w1.y, 0.f);
            w1.z = fmaxf(w1.z, 0.f); w1.w = fmaxf(w1.w, 0.f);
            float* ob = obase + f0 * 16 + h * 8;
            ((float4*)ob)[0] = w0;
            ((float4*)ob)[1] = w1;
        }
        // epilogue row 1 (predicated)
        if (two) {
            const float rinv = __fdividef(1.f, sum1);
            const uint64_t rp = pk2(rinv, rinv);
            const ulonglong2* r2 = (const ulonglong2*)(spb + OFF_R + f1 * PS + h * 8);
            ulonglong2 ru = r2[0], rv = r2[1];
            uint64_t o0 = ru.x, o1 = ru.y, o2 = rv.x, o3 = rv.y;
            fma2(o0, a10, rp); fma2(o1, a11, rp);
            fma2(o2, a12, rp); fma2(o3, a13, rp);
            float4 w0, w1;
            unpk2(o0, w0.x, w0.y); unpk2(o1, w0.z, w0.w);
            unpk2(o2, w1.x, w1.y); unpk2(o3, w1.z, w1.w);
            w0.x = fmaxf(w0.x, 0.f); w0.y = fmaxf(w0.y, 0.f);
            w0.z = fmaxf(w0.z, 0.f); w0.w = fmaxf(w0.w, 0.f);
            w1.x = fmaxf(w1.x, 0.f); w1.y = fmaxf(w1.y, 0.f);
            w1.z = fmaxf(w1.z, 0.f); w1.w = fmaxf(w1.w, 0.f);
            float* ob = obase + f1 * 16 + h * 8;
            ((float4*)ob)[0] = w0;
            ((float4*)ob)[1] = w1;
        }
    }
}

extern "C" void kernel_launch(void* const* d_in, const int* in_sizes, int n_in,
                              void* d_out, int out_size)
{
    const float* x  = (const float*)d_in[0];
    const float* Wq = (const float*)d_in[1];
    const float* Wk = (const float*)d_in[2];
    const float* Wv = (const float*)d_in[3];
    const float* Wr = (const float*)d_in[4];
    float* out = (float*)d_out;
    self_attn_interaction_kernel<<<B_TOT / 2, NT>>>(x, Wq, Wk, Wv, Wr, out);
}